// round 14
// baseline (speedup 1.0000x reference)
#include <cuda_runtime.h>
#include <math.h>
#include <stdint.h>

#define BB 8
#define NN 256
#define CC 128
#define TT 64
#define HH 4
#define GG 12
#define DD 32
#define FEPS 1e-6f
#define LOG2E 1.4426950408889634f

typedef unsigned long long ull;

// ---- f32x2 packed-math helpers ----
__device__ __forceinline__ ull pack2(float lo, float hi) {
    ull d;
    asm("mov.b64 %0, {%1, %2};" : "=l"(d)
        : "r"(__float_as_uint(lo)), "r"(__float_as_uint(hi)));
    return d;
}
__device__ __forceinline__ float2 unpack2(ull s) {
    uint32_t a, b;
    asm("mov.b64 {%0, %1}, %2;" : "=r"(a), "=r"(b) : "l"(s));
    return make_float2(__uint_as_float(a), __uint_as_float(b));
}
__device__ __forceinline__ ull fma2(ull a, ull b, ull c) {
    ull d;
    asm("fma.rn.f32x2 %0, %1, %2, %3;" : "=l"(d) : "l"(a), "l"(b), "l"(c));
    return d;
}
__device__ __forceinline__ float ex2(float x) {
    float y;
    asm("ex2.approx.ftz.f32 %0, %1;" : "=f"(y) : "f"(x));
    return y;
}
#define LDS2(a, b, addr) \
    asm volatile("ld.shared.v2.u64 {%0, %1}, [%2];" : "=l"(a), "=l"(b) : "r"(addr))
#define LDS1(a, addr) \
    asm volatile("ld.shared.u64 %0, [%1];" : "=l"(a) : "r"(addr))
#define LDG2(a, b, p) \
    asm volatile("ld.global.nc.v2.u64 {%0, %1}, [%2];" : "=l"(a), "=l"(b) : "l"(p))

// ---------------- scratch ----------------
__device__ float g_Pt[GG * CC];    // TRANSPOSED: [o][c]
__device__ float g_p0[GG];
__device__ float g_pc[CC];
__device__ float g_pc0[1];
__device__ float g_Qmt[HH * CC];   // TRANSPOSED: [h][c]
__device__ float g_q0[HH];
__device__ float g_Wrb[GG * HH];
__device__ float g_cb[HH];
__device__ float g_M[BB * GG * TT];
__device__ float g_c0[BB * TT];
__device__ float g_Vb[BB * TT * HH];
__device__ float g_q[BB * HH * NN * DD];
__device__ float g_kT[BB * HH * DD * NN];      // [b][h][d][j]
__device__ float g_v[BB * HH * NN * DD];
__device__ float g_sizes[BB * NN * 3];

// ---------------- kernel 0: weight combos — warp per output, coalesced ----------------
__global__ __launch_bounds__(256) void k_combos(
    const float* __restrict__ Wtk, const float* __restrict__ btk,
    const float* __restrict__ Wtv, const float* __restrict__ btv,
    const float* __restrict__ Wrel, const float* __restrict__ brel,
    const float* __restrict__ Wbias, const float* __restrict__ bbias)
{
    const int w = (blockIdx.x * 256 + threadIdx.x) >> 5;
    const int lane = threadIdx.x & 31;
    if (w >= 2245) return;
    const float isC = 0.08838834764831845f;  // 1/sqrt(128)

    float s = 0.f;
    if (w < 1536) {
        int o = w >> 7, cc = w & 127;
        #pragma unroll
        for (int c = lane; c < CC; c += 32) s += Wtk[cc * CC + c] * Wrel[o * CC + c];
        #pragma unroll
        for (int off = 16; off; off >>= 1) s += __shfl_xor_sync(0xffffffffu, s, off);
        if (lane == 0) g_Pt[o * CC + cc] = s * isC;
    } else if (w < 1548) {
        int g = w - 1536;
        #pragma unroll
        for (int c = lane; c < CC; c += 32) s += btk[c] * Wrel[g * CC + c];
        #pragma unroll
        for (int off = 16; off; off >>= 1) s += __shfl_xor_sync(0xffffffffu, s, off);
        if (lane == 0) g_p0[g] = s * isC;
    } else if (w < 1676) {
        int cc = w - 1548;
        #pragma unroll
        for (int c = lane; c < CC; c += 32) s += Wtk[cc * CC + c] * brel[c];
        #pragma unroll
        for (int off = 16; off; off >>= 1) s += __shfl_xor_sync(0xffffffffu, s, off);
        if (lane == 0) g_pc[cc] = s * isC;
    } else if (w == 1676) {
        #pragma unroll
        for (int c = lane; c < CC; c += 32) s += btk[c] * brel[c];
        #pragma unroll
        for (int off = 16; off; off >>= 1) s += __shfl_xor_sync(0xffffffffu, s, off);
        if (lane == 0) g_pc0[0] = s * isC;
    } else if (w < 2189) {
        int q = w - 1677; int h = q >> 7, cc = q & 127;
        #pragma unroll
        for (int c = lane; c < CC; c += 32) s += Wtv[cc * CC + c] * Wbias[c * HH + h];
        #pragma unroll
        for (int off = 16; off; off >>= 1) s += __shfl_xor_sync(0xffffffffu, s, off);
        if (lane == 0) g_Qmt[h * CC + cc] = s;
    } else if (w < 2193) {
        int h = w - 2189;
        #pragma unroll
        for (int c = lane; c < CC; c += 32) s += btv[c] * Wbias[c * HH + h];
        #pragma unroll
        for (int off = 16; off; off >>= 1) s += __shfl_xor_sync(0xffffffffu, s, off);
        if (lane == 0) g_q0[h] = s;
    } else if (w < 2241) {
        int q = w - 2193; int g = q >> 2, h = q & 3;
        #pragma unroll
        for (int c = lane; c < CC; c += 32) s += Wrel[g * CC + c] * Wbias[c * HH + h];
        #pragma unroll
        for (int off = 16; off; off >>= 1) s += __shfl_xor_sync(0xffffffffu, s, off);
        if (lane == 0) g_Wrb[q] = s;
    } else {
        int h = w - 2241;
        #pragma unroll
        for (int c = lane; c < CC; c += 32) s += brel[c] * Wbias[c * HH + h];
        #pragma unroll
        for (int off = 16; off; off >>= 1) s += __shfl_xor_sync(0xffffffffu, s, off);
        if (lane == 0) g_cb[h] = s + bbias[h];
    }
}

// ---------------- kernel 1: lang tokens -> M, c0, Vb (coalesced tables) ----------------
__global__ __launch_bounds__(128) void k_lang(const float* __restrict__ lang)
{
    const int bt = blockIdx.x;
    const int b = bt >> 6, t = bt & 63;
    const int tid = threadIdx.x;
    __shared__ float L[CC];
    L[tid] = lang[bt * CC + tid];
    __syncthreads();
    const int wid = tid >> 5, lane = tid & 31;
    for (int o = wid; o < 17; o += 4) {
        float s = 0.f;
        if (o < 12) {
            #pragma unroll
            for (int c = lane; c < CC; c += 32) s += L[c] * g_Pt[o * CC + c];
        } else if (o == 12) {
            #pragma unroll
            for (int c = lane; c < CC; c += 32) s += L[c] * g_pc[c];
        } else {
            int h = o - 13;
            #pragma unroll
            for (int c = lane; c < CC; c += 32) s += L[c] * g_Qmt[h * CC + c];
        }
        #pragma unroll
        for (int off = 16; off; off >>= 1) s += __shfl_xor_sync(0xffffffffu, s, off);
        if (lane == 0) {
            if (o < 12)       g_M[(b * GG + o) * TT + t] = s + g_p0[o];
            else if (o == 12) g_c0[b * TT + t] = s + g_pc0[0];
            else              g_Vb[(b * TT + t) * HH + (o - 13)] = s + g_q0[o - 13];
        }
    }
}

// ---------------- kernel 2: QKV projections + box sizes ----------------
__global__ __launch_bounds__(256) void k_qkv(
    const float* __restrict__ feat, const float* __restrict__ corners,
    const float* __restrict__ Wq, const float* __restrict__ bq,
    const float* __restrict__ Wk, const float* __restrict__ bk,
    const float* __restrict__ Wv, const float* __restrict__ bv)
{
    const int blk = blockIdx.x;
    const int tid = threadIdx.x;
    const int half = tid >> 7;
    const int ch = tid & 127;
    const int rbase = blk * 8;
    __shared__ float F[8][CC];
    for (int x = tid; x < 8 * CC; x += 256)
        F[x >> 7][x & 127] = feat[rbase * CC + x];
    __syncthreads();

    float aq[4], ak[4], av[4];
    #pragma unroll
    for (int r = 0; r < 4; r++) { aq[r] = bq[ch]; ak[r] = bk[ch]; av[r] = bv[ch]; }
    for (int cc = 0; cc < CC; cc++) {
        float wq = Wq[cc * CC + ch], wk = Wk[cc * CC + ch], wv = Wv[cc * CC + ch];
        #pragma unroll
        for (int r = 0; r < 4; r++) {
            float f = F[half * 4 + r][cc];
            aq[r] += f * wq; ak[r] += f * wk; av[r] += f * wv;
        }
    }
    const int h = ch >> 5, d = ch & 31;
    #pragma unroll
    for (int r = 0; r < 4; r++) {
        int bi = rbase + half * 4 + r; int b = bi >> 8, i = bi & 255;
        int o = ((b * HH + h) * NN + i) * DD + d;
        g_q[o] = aq[r]; g_v[o] = av[r];
        g_kT[((b * HH + h) * DD + d) * NN + i] = ak[r];
    }
    if (tid < 24) {
        int r = tid / 3, kd = tid % 3;
        int bi = rbase + r;
        float mx = -1e30f, mn = 1e30f;
        for (int cn = 0; cn < 8; cn++) {
            float v2 = corners[(bi * 8 + cn) * 3 + kd];
            mx = fmaxf(mx, v2); mn = fminf(mn, v2);
        }
        g_sizes[bi * 3 + kd] = mx - mn;
    }
}

// ---------------- kernel 3: fused main — 4 queries/block, occ 3 ----------------
__global__ __launch_bounds__(256, 3) void k_main(
    const float* __restrict__ centers,
    const float* __restrict__ Wo,
    const float* __restrict__ bo,
    float* __restrict__ out)
{
    const int i0 = blockIdx.x * 4;
    const int b = blockIdx.y;
    const int tid = threadIdx.x;

    __shared__ float  sRow6[6 * TT];      // rows 0..5 x LOG2E (i-independent)
    __shared__ float  sRowI[4][3 * TT];   // per-i folded rows 6..8 x LOG2E
    __shared__ float  sC0[4][TT];         // per-i folded const x LOG2E
    __shared__ float4 sVb4[TT];           // raw
    __shared__ float  sWrbF[4][9 * HH];   // per-i folded bias rows x LOG2E
    __shared__ float  sCbF[4][HH];
    __shared__ ull    sQp[4][HH][16];     // q packed pairs [ii][h][d2]
    __shared__ float4 sE4[4][NN];
    __shared__ float  sESum[4][8][HH];    // per-warp partial e-sums
    __shared__ float  sAVf[4][8][CC];
    __shared__ float4 sOFi4[CC];          // normalized AV: [c] -> (ii0..ii3)
    __shared__ float  sOP[4][2][CC];

    float* sE = (float*)sE4;
    float* sOFi = (float*)sOFi4;

    const float* Mb = g_M + b * (GG * TT);

    // ---- setup: one barrier ----
    for (int x = tid; x < 6 * TT; x += 256) sRow6[x] = Mb[x] * LOG2E;
    ((float*)sVb4)[tid] = g_Vb[b * TT * HH + tid];
    {
        // pack q for QK: thread -> (ii, h, d2)
        const int ii = tid >> 6, h = (tid >> 4) & 3, d2 = tid & 15;
        float2 qv = *(const float2*)(g_q + ((size_t)(b * HH + h) * NN + i0 + ii) * DD + 2 * d2);
        sQp[ii][h][d2] = pack2(qv.x, qv.y);
    }
    {
        const int ii = tid >> 6, t = tid & 63;
        const float* ctp = centers + (b * NN + i0 + ii) * 3;
        const float* szp = g_sizes + (b * NN + i0 + ii) * 3;
        float ct0 = ctp[0], ct1 = ctp[1], ct2 = ctp[2];
        float sz0 = szp[0], sz1 = szp[1], sz2 = szp[2];
        float inv0 = __fdividef(1.f, sz0 + FEPS);
        float inv1 = __fdividef(1.f, sz1 + FEPS);
        float inv2 = __fdividef(1.f, sz2 + FEPS);
        float m6 = Mb[6 * TT + t],  m7 = Mb[7 * TT + t],  m8 = Mb[8 * TT + t];
        float m9 = Mb[9 * TT + t], m10 = Mb[10 * TT + t], m11 = Mb[11 * TT + t];
        float c0 = (g_c0[b * TT + t]
                 - ct0 * Mb[0 * TT + t] - ct1 * Mb[1 * TT + t] - ct2 * Mb[2 * TT + t]
                 - sz0 * m6 - sz1 * m7 - sz2 * m8) * LOG2E;
        sC0[ii][t] = c0;
        sRowI[ii][0 * TT + t] = (m6 + inv0 * m9) * LOG2E;
        sRowI[ii][1 * TT + t] = (m7 + inv1 * m10) * LOG2E;
        sRowI[ii][2 * TT + t] = (m8 + inv2 * m11) * LOG2E;
    }
    if (tid < 144) {
        const int ii = tid / 36; const int qq = tid % 36;
        const int g = qq >> 2, h = qq & 3;
        float w = g_Wrb[g * HH + h];
        if (g >= 6) {
            float sz = g_sizes[(b * NN + i0 + ii) * 3 + (g - 6)];
            w += __fdividef(1.f, sz + FEPS) * g_Wrb[(g + 3) * HH + h];
        }
        sWrbF[ii][qq] = w * LOG2E;
    }
    if (tid < 16) {
        const int ii = tid >> 2, h = tid & 3;
        const float* ctp = centers + (b * NN + i0 + ii) * 3;
        const float* szp = g_sizes + (b * NN + i0 + ii) * 3;
        float c = g_cb[h];
        #pragma unroll
        for (int kk = 0; kk < 3; kk++)
            c -= ctp[kk] * g_Wrb[kk * HH + h] + szp[kk] * g_Wrb[(6 + kk) * HH + h];
        sCbF[ii][h] = c * LOG2E;
    }
    __syncthreads();

    // ---- per-thread geometry (j = tid) ----
    const int j = tid;
    float cjx = centers[(b * NN + j) * 3 + 0];
    float cjy = centers[(b * NN + j) * 3 + 1];
    float cjz = centers[(b * NN + j) * 3 + 2];
    float sj0 = g_sizes[(b * NN + j) * 3 + 0];
    float sj1 = g_sizes[(b * NN + j) * 3 + 1];
    float sj2 = g_sizes[(b * NN + j) * 3 + 2];
    ull cvS[6];
    cvS[0] = pack2(cjx, cjx); cvS[1] = pack2(cjy, cjy); cvS[2] = pack2(cjz, cjz);
    cvS[3] = pack2(sj0, sj0); cvS[4] = pack2(sj1, sj1); cvS[5] = pack2(sj2, sj2);
    ull cvI[4][3];
    #pragma unroll
    for (int ii = 0; ii < 4; ii++) {
        const float* ctp = centers + (b * NN + i0 + ii) * 3;
        float rx = cjx - ctp[0], ry = cjy - ctp[1], rz = cjz - ctp[2];
        float r2all = rx * rx + ry * ry + rz * rz;
        float r2h   = rx * rx + ry * ry;
        float dist  = r2all * rsqrtf(r2all + 1e-30f);
        float horiz = r2h * rsqrtf(r2h + 1e-30f);
        float dl = __logf(dist + FEPS);
        float ce = __fdividef(rz, dist + FEPS);
        cvI[ii][0] = pack2(dl, dl);
        cvI[ii][1] = pack2(horiz, horiz);
        cvI[ii][2] = pack2(ce, ce);
    }

    const uint32_t row6Addr = (uint32_t)__cvta_generic_to_shared(sRow6);
    const uint32_t rowIAddr = (uint32_t)__cvta_generic_to_shared(sRowI);
    const uint32_t c0Addr   = (uint32_t)__cvta_generic_to_shared(sC0);
    const uint32_t vbAddr   = (uint32_t)__cvta_generic_to_shared(sVb4);
    const uint32_t wrbAddr  = (uint32_t)__cvta_generic_to_shared(sWrbF);
    const uint32_t qpAddr   = (uint32_t)__cvta_generic_to_shared(sQp);

    // ---- token scores + softmax accumulation for 4 i ----
    float ssum[4] = {0.f, 0.f, 0.f, 0.f};
    ull aA[4] = {0,0,0,0}, aB[4] = {0,0,0,0};
    #pragma unroll
    for (int c = 0; c < 8; c++) {       // 8 chunks of 8 tokens
        ull s0[4][4];
        #pragma unroll
        for (int ii = 0; ii < 4; ii++) {
            LDS2(s0[ii][0], s0[ii][1], c0Addr + ii * (TT * 4) + c * 32);
            LDS2(s0[ii][2], s0[ii][3], c0Addr + ii * (TT * 4) + c * 32 + 16);
        }
        #pragma unroll
        for (int g = 0; g < 3; g++) {
            ull r0, r1, r2, r3;
            LDS2(r0, r1, row6Addr + g * 256 + c * 32);
            LDS2(r2, r3, row6Addr + g * 256 + c * 32 + 16);
            #pragma unroll
            for (int ii = 0; ii < 4; ii++) {
                s0[ii][0] = fma2(cvS[g], r0, s0[ii][0]);
                s0[ii][1] = fma2(cvS[g], r1, s0[ii][1]);
                s0[ii][2] = fma2(cvS[g], r2, s0[ii][2]);
                s0[ii][3] = fma2(cvS[g], r3, s0[ii][3]);
            }
        }
        #pragma unroll
        for (int g = 0; g < 3; g++) {
            ull r0, r1, r2, r3;
            LDS2(r0, r1, row6Addr + (g + 3) * 256 + c * 32);
            LDS2(r2, r3, row6Addr + (g + 3) * 256 + c * 32 + 16);
            #pragma unroll
            for (int ii = 0; ii < 4; ii++) {
                s0[ii][0] = fma2(cvI[ii][g], r0, s0[ii][0]);
                s0[ii][1] = fma2(cvI[ii][g], r1, s0[ii][1]);
                s0[ii][2] = fma2(cvI[ii][g], r2, s0[ii][2]);
                s0[ii][3] = fma2(cvI[ii][g], r3, s0[ii][3]);
            }
        }
        #pragma unroll
        for (int g = 0; g < 3; g++) {
            #pragma unroll
            for (int ii = 0; ii < 4; ii++) {
                ull r0, r1, r2, r3;
                LDS2(r0, r1, rowIAddr + ii * (3 * TT * 4) + g * 256 + c * 32);
                LDS2(r2, r3, rowIAddr + ii * (3 * TT * 4) + g * 256 + c * 32 + 16);
                s0[ii][0] = fma2(cvS[3 + g], r0, s0[ii][0]);
                s0[ii][1] = fma2(cvS[3 + g], r1, s0[ii][1]);
                s0[ii][2] = fma2(cvS[3 + g], r2, s0[ii][2]);
                s0[ii][3] = fma2(cvS[3 + g], r3, s0[ii][3]);
            }
        }
        #pragma unroll
        for (int k = 0; k < 4; k++) {   // each k handles 2 tokens
            int t0 = c * 8 + k * 2;
            ull vA0, vB0, vA1, vB1;
            LDS2(vA0, vB0, vbAddr + t0 * 16);
            LDS2(vA1, vB1, vbAddr + t0 * 16 + 16);
            #pragma unroll
            for (int ii = 0; ii < 4; ii++) {
                float2 v = unpack2(s0[ii][k]);
                float e0 = ex2(v.x);
                float e1 = ex2(v.y);
                ssum[ii] += e0 + e1;
                ull e02 = pack2(e0, e0);
                ull e12 = pack2(e1, e1);
                aA[ii] = fma2(e02, vA0, aA[ii]); aB[ii] = fma2(e02, vB0, aB[ii]);
                aA[ii] = fma2(e12, vA1, aA[ii]); aB[ii] = fma2(e12, vB1, aB[ii]);
            }
        }
    }

    // ---- bias + ctx per (ii,h) -> bc[ii][h]; frees accumulators before QK ----
    float bc[4][HH];
    #pragma unroll
    for (int ii = 0; ii < 4; ii++) {
        ull bA = pack2(sCbF[ii][0], sCbF[ii][1]);
        ull bB = pack2(sCbF[ii][2], sCbF[ii][3]);
        const uint32_t wa = wrbAddr + ii * (9 * HH * 4);
        ull wA, wB;
        LDS2(wA, wB, wa + 0 * 16);  bA = fma2(cvS[0], wA, bA); bB = fma2(cvS[0], wB, bB);
        LDS2(wA, wB, wa + 1 * 16);  bA = fma2(cvS[1], wA, bA); bB = fma2(cvS[1], wB, bB);
        LDS2(wA, wB, wa + 2 * 16);  bA = fma2(cvS[2], wA, bA); bB = fma2(cvS[2], wB, bB);
        LDS2(wA, wB, wa + 3 * 16);  bA = fma2(cvI[ii][0], wA, bA); bB = fma2(cvI[ii][0], wB, bB);
        LDS2(wA, wB, wa + 4 * 16);  bA = fma2(cvI[ii][1], wA, bA); bB = fma2(cvI[ii][1], wB, bB);
        LDS2(wA, wB, wa + 5 * 16);  bA = fma2(cvI[ii][2], wA, bA); bB = fma2(cvI[ii][2], wB, bB);
        LDS2(wA, wB, wa + 6 * 16);  bA = fma2(cvS[3], wA, bA); bB = fma2(cvS[3], wB, bB);
        LDS2(wA, wB, wa + 7 * 16);  bA = fma2(cvS[4], wA, bA); bB = fma2(cvS[4], wB, bB);
        LDS2(wA, wB, wa + 8 * 16);  bA = fma2(cvS[5], wA, bA); bB = fma2(cvS[5], wB, bB);
        float2 b01 = unpack2(bA), b23 = unpack2(bB);
        float invL = __fdividef(1.f, ssum[ii]) * LOG2E;
        float2 a01 = unpack2(aA[ii]), a23 = unpack2(aB[ii]);
        bc[ii][0] = b01.x + a01.x * invL;
        bc[ii][1] = b01.y + a01.y * invL;
        bc[ii][2] = b23.x + a23.x * invL;
        bc[ii][3] = b23.y + a23.y * invL;
    }

    // ---- QK per head: chunked K loads (kk[8]), 4 ii chains, fused exp ----
    const float SC = 0.17677669529663687f * LOG2E;  // 1/sqrt(32) * log2(e)
    #pragma unroll
    for (int h = 0; h < HH; h++) {
        const float* kc = g_kT + (size_t)(b * HH + h) * DD * NN + j;
        ull acc[4] = {0ull, 0ull, 0ull, 0ull};
        #pragma unroll
        for (int dh = 0; dh < 2; dh++) {
            ull kk[8];
            #pragma unroll
            for (int p = 0; p < 8; p++)
                kk[p] = pack2(kc[(dh * 16 + 2 * p) * NN], kc[(dh * 16 + 2 * p + 1) * NN]);
            #pragma unroll
            for (int ii = 0; ii < 4; ii++) {
                #pragma unroll
                for (int p = 0; p < 8; p += 2) {
                    ull q0, q1;
                    LDS2(q0, q1, qpAddr + ((ii * HH + h) * 16 + dh * 8 + p) * 8);
                    acc[ii] = fma2(kk[p], q0, acc[ii]);
                    acc[ii] = fma2(kk[p + 1], q1, acc[ii]);
                }
            }
        }
        #pragma unroll
        for (int ii = 0; ii < 4; ii++) {
            float2 r = unpack2(acc[ii]);
            float e = ex2((r.x + r.y) * SC + bc[ii][h]);
            sE[ii * (NN * 4) + tid * 4 + h] = e;
        }
    }
    __syncthreads();

    // ---- AV: V loads shared by 4 i; e-sums folded in ----
    const int wid = tid >> 5, lane = tid & 31;
    {
        const int h = lane >> 3, d4 = lane & 7;
        const float* vp = g_v + (size_t)(b * HH + h) * NN * DD + d4 * 4;
        ull acc[4][2] = {{0,0},{0,0},{0,0},{0,0}};
        float eacc[4] = {0.f, 0.f, 0.f, 0.f};
        #pragma unroll 8
        for (int jj = 0; jj < 32; jj++) {
            int j2 = wid * 32 + jj;
            ull vA, vB;
            LDG2(vA, vB, vp + (size_t)j2 * DD);
            #pragma unroll
            for (int ii = 0; ii < 4; ii++) {
                float e = sE[ii * (NN * 4) + j2 * 4 + h];
                eacc[ii] += e;
                ull e2 = pack2(e, e);
                acc[ii][0] = fma2(e2, vA, acc[ii][0]);
                acc[ii][1] = fma2(e2, vB, acc[ii][1]);
            }
        }
        #pragma unroll
        for (int ii = 0; ii < 4; ii++) {
            ull* dst = (ull*)&sAVf[ii][wid][lane * 4];
            dst[0] = acc[ii][0]; dst[1] = acc[ii][1];
        }
        if (d4 == 0) {
            #pragma unroll
            for (int ii = 0; ii < 4; ii++) sESum[ii][wid][h] = eacc[ii];
        }
    }
    __syncthreads();
    // ---- normalize: 4 i x 128 c = 512 items, 2 per thread ----
    #pragma unroll
    for (int p = 0; p < 2; p++) {
        const int ii = (tid >> 7) * 2 + p;
        const int c = tid & 127;
        const int h = c >> 5, d = c & 31;
        float s = 0.f;
        float denom = 0.f;
        #pragma unroll
        for (int w = 0; w < 8; w++) {
            s += sAVf[ii][w][h * 32 + d];
            denom += sESum[ii][w][h];
        }
        sOFi[c * 4 + ii] = __fdividef(s, denom);
    }
    __syncthreads();

    // ---- output projection: one LDS2 serves all 4 i per Wo element ----
    {
        const int c = tid & 127;
        const int half = tid >> 7;
        const float* wp = Wo + (half * 64) * CC + c;
        const uint32_t ofAddr = (uint32_t)__cvta_generic_to_shared(sOFi4) + half * 64 * 16;
        ull accA = 0ull, accB = 0ull;
        #pragma unroll 8
        for (int cc2 = 0; cc2 < 64; cc2++) {
            float w = wp[cc2 * CC];
            ull o01, o23;
            LDS2(o01, o23, ofAddr + cc2 * 16);
            ull w2 = pack2(w, w);
            accA = fma2(o01, w2, accA);
            accB = fma2(o23, w2, accB);
        }
        float2 rA = unpack2(accA), rB = unpack2(accB);
        sOP[0][half][c] = rA.x;
        sOP[1][half][c] = rA.y;
        sOP[2][half][c] = rB.x;
        sOP[3][half][c] = rB.y;
    }
    __syncthreads();
    #pragma unroll
    for (int p = 0; p < 2; p++) {
        const int ii = (tid >> 7) * 2 + p;
        const int c = tid & 127;
        out[(b * NN + i0 + ii) * CC + c] = bo[c] + sOP[ii][0][c] + sOP[ii][1][c];
    }
}

// ---------------- launch ----------------
extern "C" void kernel_launch(void* const* d_in, const int* in_sizes, int n_in,
                              void* d_out, int out_size)
{
    const float* feat    = (const float*)d_in[0];
    const float* centers = (const float*)d_in[1];
    const float* corners = (const float*)d_in[2];
    const float* lang    = (const float*)d_in[3];
    const float* Wq    = (const float*)d_in[4];
    const float* bq    = (const float*)d_in[5];
    const float* Wk    = (const float*)d_in[6];
    const float* bk    = (const float*)d_in[7];
    const float* Wv    = (const float*)d_in[8];
    const float* bv    = (const float*)d_in[9];
    const float* Wo    = (const float*)d_in[10];
    const float* bo    = (const float*)d_in[11];
    const float* Wrel  = (const float*)d_in[12];
    const float* brel  = (const float*)d_in[13];
    const float* Wtk   = (const float*)d_in[14];
    const float* btk   = (const float*)d_in[15];
    const float* Wtv   = (const float*)d_in[16];
    const float* btv   = (const float*)d_in[17];
    const float* Wbias = (const float*)d_in[18];
    const float* bbias = (const float*)d_in[19];

    k_combos<<<281, 256>>>(Wtk, btk, Wtv, btv, Wrel, brel, Wbias, bbias);
    k_lang<<<BB * TT, 128>>>(lang);
    k_qkv<<<BB * NN / 8, 256>>>(feat, corners, Wq, bq, Wk, bk, Wv, bv);
    k_main<<<dim3(NN / 4, BB), 256>>>(centers, Wo, bo, (float*)d_out);
}

// round 15
// speedup vs baseline: 1.0726x; 1.0726x over previous
#include <cuda_runtime.h>
#include <math.h>
#include <stdint.h>

#define BB 8
#define NN 256
#define CC 128
#define TT 64
#define HH 4
#define GG 12
#define DD 32
#define FEPS 1e-6f
#define LOG2E 1.4426950408889634f

typedef unsigned long long ull;

// ---- f32x2 packed-math helpers ----
__device__ __forceinline__ ull pack2(float lo, float hi) {
    ull d;
    asm("mov.b64 %0, {%1, %2};" : "=l"(d)
        : "r"(__float_as_uint(lo)), "r"(__float_as_uint(hi)));
    return d;
}
__device__ __forceinline__ float2 unpack2(ull s) {
    uint32_t a, b;
    asm("mov.b64 {%0, %1}, %2;" : "=r"(a), "=r"(b) : "l"(s));
    return make_float2(__uint_as_float(a), __uint_as_float(b));
}
__device__ __forceinline__ ull fma2(ull a, ull b, ull c) {
    ull d;
    asm("fma.rn.f32x2 %0, %1, %2, %3;" : "=l"(d) : "l"(a), "l"(b), "l"(c));
    return d;
}
__device__ __forceinline__ float ex2(float x) {
    float y;
    asm("ex2.approx.ftz.f32 %0, %1;" : "=f"(y) : "f"(x));
    return y;
}
#define LDS2(a, b, addr) \
    asm volatile("ld.shared.v2.u64 {%0, %1}, [%2];" : "=l"(a), "=l"(b) : "r"(addr))
#define LDG2(a, b, p) \
    asm volatile("ld.global.nc.v2.u64 {%0, %1}, [%2];" : "=l"(a), "=l"(b) : "l"(p))

// ---------------- scratch ----------------
__device__ float g_Pt[GG * CC];    // TRANSPOSED: [o][c]
__device__ float g_p0[GG];
__device__ float g_pc[CC];
__device__ float g_pc0[1];
__device__ float g_Qmt[HH * CC];   // TRANSPOSED: [h][c]
__device__ float g_q0[HH];
__device__ float g_Wrb[GG * HH];
__device__ float g_cb[HH];
__device__ float g_M[BB * GG * TT];
__device__ float g_c0[BB * TT];
__device__ float g_Vb[BB * TT * HH];
__device__ float g_q[BB * HH * NN * DD];
__device__ float g_kT[BB * HH * DD * NN];      // [b][h][d][j]
__device__ float g_v[BB * HH * NN * DD];
__device__ float g_sizes[BB * NN * 3];

// ---------------- kernel 0: weight combos — warp per output, coalesced ----------------
__global__ __launch_bounds__(256) void k_combos(
    const float* __restrict__ Wtk, const float* __restrict__ btk,
    const float* __restrict__ Wtv, const float* __restrict__ btv,
    const float* __restrict__ Wrel, const float* __restrict__ brel,
    const float* __restrict__ Wbias, const float* __restrict__ bbias)
{
    const int w = (blockIdx.x * 256 + threadIdx.x) >> 5;
    const int lane = threadIdx.x & 31;
    if (w >= 2245) return;
    const float isC = 0.08838834764831845f;  // 1/sqrt(128)

    float s = 0.f;
    if (w < 1536) {
        int o = w >> 7, cc = w & 127;
        #pragma unroll
        for (int c = lane; c < CC; c += 32) s += Wtk[cc * CC + c] * Wrel[o * CC + c];
        #pragma unroll
        for (int off = 16; off; off >>= 1) s += __shfl_xor_sync(0xffffffffu, s, off);
        if (lane == 0) g_Pt[o * CC + cc] = s * isC;
    } else if (w < 1548) {
        int g = w - 1536;
        #pragma unroll
        for (int c = lane; c < CC; c += 32) s += btk[c] * Wrel[g * CC + c];
        #pragma unroll
        for (int off = 16; off; off >>= 1) s += __shfl_xor_sync(0xffffffffu, s, off);
        if (lane == 0) g_p0[g] = s * isC;
    } else if (w < 1676) {
        int cc = w - 1548;
        #pragma unroll
        for (int c = lane; c < CC; c += 32) s += Wtk[cc * CC + c] * brel[c];
        #pragma unroll
        for (int off = 16; off; off >>= 1) s += __shfl_xor_sync(0xffffffffu, s, off);
        if (lane == 0) g_pc[cc] = s * isC;
    } else if (w == 1676) {
        #pragma unroll
        for (int c = lane; c < CC; c += 32) s += btk[c] * brel[c];
        #pragma unroll
        for (int off = 16; off; off >>= 1) s += __shfl_xor_sync(0xffffffffu, s, off);
        if (lane == 0) g_pc0[0] = s * isC;
    } else if (w < 2189) {
        int q = w - 1677; int h = q >> 7, cc = q & 127;
        #pragma unroll
        for (int c = lane; c < CC; c += 32) s += Wtv[cc * CC + c] * Wbias[c * HH + h];
        #pragma unroll
        for (int off = 16; off; off >>= 1) s += __shfl_xor_sync(0xffffffffu, s, off);
        if (lane == 0) g_Qmt[h * CC + cc] = s;
    } else if (w < 2193) {
        int h = w - 2189;
        #pragma unroll
        for (int c = lane; c < CC; c += 32) s += btv[c] * Wbias[c * HH + h];
        #pragma unroll
        for (int off = 16; off; off >>= 1) s += __shfl_xor_sync(0xffffffffu, s, off);
        if (lane == 0) g_q0[h] = s;
    } else if (w < 2241) {
        int q = w - 2193; int g = q >> 2, h = q & 3;
        #pragma unroll
        for (int c = lane; c < CC; c += 32) s += Wrel[g * CC + c] * Wbias[c * HH + h];
        #pragma unroll
        for (int off = 16; off; off >>= 1) s += __shfl_xor_sync(0xffffffffu, s, off);
        if (lane == 0) g_Wrb[q] = s;
    } else {
        int h = w - 2241;
        #pragma unroll
        for (int c = lane; c < CC; c += 32) s += brel[c] * Wbias[c * HH + h];
        #pragma unroll
        for (int off = 16; off; off >>= 1) s += __shfl_xor_sync(0xffffffffu, s, off);
        if (lane == 0) g_cb[h] = s + bbias[h];
    }
}

// ---------------- kernel 1: lang tokens -> M, c0, Vb (coalesced tables) ----------------
__global__ __launch_bounds__(128) void k_lang(const float* __restrict__ lang)
{
    const int bt = blockIdx.x;
    const int b = bt >> 6, t = bt & 63;
    const int tid = threadIdx.x;
    __shared__ float L[CC];
    L[tid] = lang[bt * CC + tid];
    __syncthreads();
    const int wid = tid >> 5, lane = tid & 31;
    for (int o = wid; o < 17; o += 4) {
        float s = 0.f;
        if (o < 12) {
            #pragma unroll
            for (int c = lane; c < CC; c += 32) s += L[c] * g_Pt[o * CC + c];
        } else if (o == 12) {
            #pragma unroll
            for (int c = lane; c < CC; c += 32) s += L[c] * g_pc[c];
        } else {
            int h = o - 13;
            #pragma unroll
            for (int c = lane; c < CC; c += 32) s += L[c] * g_Qmt[h * CC + c];
        }
        #pragma unroll
        for (int off = 16; off; off >>= 1) s += __shfl_xor_sync(0xffffffffu, s, off);
        if (lane == 0) {
            if (o < 12)       g_M[(b * GG + o) * TT + t] = s + g_p0[o];
            else if (o == 12) g_c0[b * TT + t] = s + g_pc0[0];
            else              g_Vb[(b * TT + t) * HH + (o - 13)] = s + g_q0[o - 13];
        }
    }
}

// ---------------- kernel 2: QKV projections + box sizes (channel-pair fma2) ----------------
// 256 blocks x 256 threads; thread = (channel-pair chp, row-group rg of 2 rows).
__global__ __launch_bounds__(256) void k_qkv(
    const float* __restrict__ feat, const float* __restrict__ corners,
    const float* __restrict__ Wq, const float* __restrict__ bq,
    const float* __restrict__ Wk, const float* __restrict__ bk,
    const float* __restrict__ Wv, const float* __restrict__ bv)
{
    const int blk = blockIdx.x;
    const int tid = threadIdx.x;
    const int chp = tid & 63;        // channel pair
    const int rg  = tid >> 6;        // row group (2 rows)
    const int rbase = blk * 8;
    __shared__ float F[8][CC];
    for (int x = tid; x < 8 * CC; x += 256)
        F[x >> 7][x & 127] = feat[rbase * CC + x];
    __syncthreads();

    const int c0 = 2 * chp;
    ull aq[2], ak[2], av[2];
    {
        ull bq2 = pack2(bq[c0], bq[c0 + 1]);
        ull bk2 = pack2(bk[c0], bk[c0 + 1]);
        ull bv2 = pack2(bv[c0], bv[c0 + 1]);
        aq[0] = aq[1] = bq2; ak[0] = ak[1] = bk2; av[0] = av[1] = bv2;
    }
    for (int cc = 0; cc < CC; cc++) {
        float2 wq = *(const float2*)(Wq + cc * CC + c0);
        float2 wk = *(const float2*)(Wk + cc * CC + c0);
        float2 wv = *(const float2*)(Wv + cc * CC + c0);
        ull wq2 = pack2(wq.x, wq.y);
        ull wk2 = pack2(wk.x, wk.y);
        ull wv2 = pack2(wv.x, wv.y);
        #pragma unroll
        for (int r = 0; r < 2; r++) {
            float f = F[rg * 2 + r][cc];
            ull f2 = pack2(f, f);
            aq[r] = fma2(wq2, f2, aq[r]);
            ak[r] = fma2(wk2, f2, ak[r]);
            av[r] = fma2(wv2, f2, av[r]);
        }
    }
    const int h = c0 >> 5, d0 = c0 & 31;
    #pragma unroll
    for (int r = 0; r < 2; r++) {
        int bi = rbase + rg * 2 + r; int b = bi >> 8, i = bi & 255;
        size_t o = ((size_t)(b * HH + h) * NN + i) * DD + d0;
        float2 qv = unpack2(aq[r]);
        float2 vv = unpack2(av[r]);
        float2 kv = unpack2(ak[r]);
        *(float2*)(g_q + o) = qv;
        *(float2*)(g_v + o) = vv;
        g_kT[((size_t)(b * HH + h) * DD + d0) * NN + i] = kv.x;
        g_kT[((size_t)(b * HH + h) * DD + d0 + 1) * NN + i] = kv.y;
    }
    if (tid < 24) {
        int r = tid / 3, kd = tid % 3;
        int bi = rbase + r;
        float mx = -1e30f, mn = 1e30f;
        for (int cn = 0; cn < 8; cn++) {
            float v2 = corners[(bi * 8 + cn) * 3 + kd];
            mx = fmaxf(mx, v2); mn = fminf(mn, v2);
        }
        g_sizes[bi * 3 + kd] = mx - mn;
    }
}

// ---------------- kernel 3: fused main — 4 queries/block, (256,2), sE as [j][h]->ii4 ----------------
__global__ __launch_bounds__(256, 2) void k_main(
    const float* __restrict__ centers,
    const float* __restrict__ Wo,
    const float* __restrict__ bo,
    float* __restrict__ out)
{
    const int i0 = blockIdx.x * 4;
    const int b = blockIdx.y;
    const int tid = threadIdx.x;

    __shared__ float  sRow6[6 * TT];      // rows 0..5 x LOG2E (i-independent)
    __shared__ float  sRowI[4][3 * TT];   // per-i folded rows 6..8 x LOG2E
    __shared__ float  sC0[4][TT];         // per-i folded const x LOG2E
    __shared__ float4 sVb4[TT];           // raw
    __shared__ float  sWrbF[4][9 * HH];   // per-i folded bias rows x LOG2E
    __shared__ float  sCbF[4][HH];
    __shared__ ull    sQp[4][HH][16];     // q packed pairs [ii][h][d2]
    __shared__ float4 sEn[NN][HH];        // e: [j][h] -> (ii0..ii3)
    __shared__ float  sESum[4][8][HH];    // per-warp partial e-sums
    __shared__ float  sAVf[4][8][CC];
    __shared__ float4 sOFi4[CC];          // normalized AV: [c] -> (ii0..ii3)
    __shared__ float  sOP[4][2][CC];

    float* sOFi = (float*)sOFi4;

    const float* Mb = g_M + b * (GG * TT);

    // ---- setup: one barrier ----
    for (int x = tid; x < 6 * TT; x += 256) sRow6[x] = Mb[x] * LOG2E;
    ((float*)sVb4)[tid] = g_Vb[b * TT * HH + tid];
    {
        // pack q for QK: thread -> (ii, h, d2)
        const int ii = tid >> 6, h = (tid >> 4) & 3, d2 = tid & 15;
        float2 qv = *(const float2*)(g_q + ((size_t)(b * HH + h) * NN + i0 + ii) * DD + 2 * d2);
        sQp[ii][h][d2] = pack2(qv.x, qv.y);
    }
    {
        const int ii = tid >> 6, t = tid & 63;
        const float* ctp = centers + (b * NN + i0 + ii) * 3;
        const float* szp = g_sizes + (b * NN + i0 + ii) * 3;
        float ct0 = ctp[0], ct1 = ctp[1], ct2 = ctp[2];
        float sz0 = szp[0], sz1 = szp[1], sz2 = szp[2];
        float inv0 = __fdividef(1.f, sz0 + FEPS);
        float inv1 = __fdividef(1.f, sz1 + FEPS);
        float inv2 = __fdividef(1.f, sz2 + FEPS);
        float m6 = Mb[6 * TT + t],  m7 = Mb[7 * TT + t],  m8 = Mb[8 * TT + t];
        float m9 = Mb[9 * TT + t], m10 = Mb[10 * TT + t], m11 = Mb[11 * TT + t];
        float c0 = (g_c0[b * TT + t]
                 - ct0 * Mb[0 * TT + t] - ct1 * Mb[1 * TT + t] - ct2 * Mb[2 * TT + t]
                 - sz0 * m6 - sz1 * m7 - sz2 * m8) * LOG2E;
        sC0[ii][t] = c0;
        sRowI[ii][0 * TT + t] = (m6 + inv0 * m9) * LOG2E;
        sRowI[ii][1 * TT + t] = (m7 + inv1 * m10) * LOG2E;
        sRowI[ii][2 * TT + t] = (m8 + inv2 * m11) * LOG2E;
    }
    if (tid < 144) {
        const int ii = tid / 36; const int qq = tid % 36;
        const int g = qq >> 2, h = qq & 3;
        float w = g_Wrb[g * HH + h];
        if (g >= 6) {
            float sz = g_sizes[(b * NN + i0 + ii) * 3 + (g - 6)];
            w += __fdividef(1.f, sz + FEPS) * g_Wrb[(g + 3) * HH + h];
        }
        sWrbF[ii][qq] = w * LOG2E;
    }
    if (tid < 16) {
        const int ii = tid >> 2, h = tid & 3;
        const float* ctp = centers + (b * NN + i0 + ii) * 3;
        const float* szp = g_sizes + (b * NN + i0 + ii) * 3;
        float c = g_cb[h];
        #pragma unroll
        for (int kk = 0; kk < 3; kk++)
            c -= ctp[kk] * g_Wrb[kk * HH + h] + szp[kk] * g_Wrb[(6 + kk) * HH + h];
        sCbF[ii][h] = c * LOG2E;
    }
    __syncthreads();

    // ---- per-thread geometry (j = tid) ----
    const int j = tid;
    float cjx = centers[(b * NN + j) * 3 + 0];
    float cjy = centers[(b * NN + j) * 3 + 1];
    float cjz = centers[(b * NN + j) * 3 + 2];
    float sj0 = g_sizes[(b * NN + j) * 3 + 0];
    float sj1 = g_sizes[(b * NN + j) * 3 + 1];
    float sj2 = g_sizes[(b * NN + j) * 3 + 2];
    ull cvS[6];
    cvS[0] = pack2(cjx, cjx); cvS[1] = pack2(cjy, cjy); cvS[2] = pack2(cjz, cjz);
    cvS[3] = pack2(sj0, sj0); cvS[4] = pack2(sj1, sj1); cvS[5] = pack2(sj2, sj2);
    ull cvI[4][3];
    #pragma unroll
    for (int ii = 0; ii < 4; ii++) {
        const float* ctp = centers + (b * NN + i0 + ii) * 3;
        float rx = cjx - ctp[0], ry = cjy - ctp[1], rz = cjz - ctp[2];
        float r2all = rx * rx + ry * ry + rz * rz;
        float r2h   = rx * rx + ry * ry;
        float dist  = r2all * rsqrtf(r2all + 1e-30f);
        float horiz = r2h * rsqrtf(r2h + 1e-30f);
        float dl = __logf(dist + FEPS);
        float ce = __fdividef(rz, dist + FEPS);
        cvI[ii][0] = pack2(dl, dl);
        cvI[ii][1] = pack2(horiz, horiz);
        cvI[ii][2] = pack2(ce, ce);
    }

    const uint32_t row6Addr = (uint32_t)__cvta_generic_to_shared(sRow6);
    const uint32_t rowIAddr = (uint32_t)__cvta_generic_to_shared(sRowI);
    const uint32_t c0Addr   = (uint32_t)__cvta_generic_to_shared(sC0);
    const uint32_t vbAddr   = (uint32_t)__cvta_generic_to_shared(sVb4);
    const uint32_t wrbAddr  = (uint32_t)__cvta_generic_to_shared(sWrbF);
    const uint32_t qpAddr   = (uint32_t)__cvta_generic_to_shared(sQp);

    // ---- token scores + softmax accumulation for 4 i ----
    float ssum[4] = {0.f, 0.f, 0.f, 0.f};
    ull aA[4] = {0,0,0,0}, aB[4] = {0,0,0,0};
    #pragma unroll
    for (int c = 0; c < 8; c++) {       // 8 chunks of 8 tokens
        ull s0[4][4];
        #pragma unroll
        for (int ii = 0; ii < 4; ii++) {
            LDS2(s0[ii][0], s0[ii][1], c0Addr + ii * (TT * 4) + c * 32);
            LDS2(s0[ii][2], s0[ii][3], c0Addr + ii * (TT * 4) + c * 32 + 16);
        }
        #pragma unroll
        for (int g = 0; g < 3; g++) {
            ull r0, r1, r2, r3;
            LDS2(r0, r1, row6Addr + g * 256 + c * 32);
            LDS2(r2, r3, row6Addr + g * 256 + c * 32 + 16);
            #pragma unroll
            for (int ii = 0; ii < 4; ii++) {
                s0[ii][0] = fma2(cvS[g], r0, s0[ii][0]);
                s0[ii][1] = fma2(cvS[g], r1, s0[ii][1]);
                s0[ii][2] = fma2(cvS[g], r2, s0[ii][2]);
                s0[ii][3] = fma2(cvS[g], r3, s0[ii][3]);
            }
        }
        #pragma unroll
        for (int g = 0; g < 3; g++) {
            ull r0, r1, r2, r3;
            LDS2(r0, r1, row6Addr + (g + 3) * 256 + c * 32);
            LDS2(r2, r3, row6Addr + (g + 3) * 256 + c * 32 + 16);
            #pragma unroll
            for (int ii = 0; ii < 4; ii++) {
                s0[ii][0] = fma2(cvI[ii][g], r0, s0[ii][0]);
                s0[ii][1] = fma2(cvI[ii][g], r1, s0[ii][1]);
                s0[ii][2] = fma2(cvI[ii][g], r2, s0[ii][2]);
                s0[ii][3] = fma2(cvI[ii][g], r3, s0[ii][3]);
            }
        }
        #pragma unroll
        for (int g = 0; g < 3; g++) {
            #pragma unroll
            for (int ii = 0; ii < 4; ii++) {
                ull r0, r1, r2, r3;
                LDS2(r0, r1, rowIAddr + ii * (3 * TT * 4) + g * 256 + c * 32);
                LDS2(r2, r3, rowIAddr + ii * (3 * TT * 4) + g * 256 + c * 32 + 16);
                s0[ii][0] = fma2(cvS[3 + g], r0, s0[ii][0]);
                s0[ii][1] = fma2(cvS[3 + g], r1, s0[ii][1]);
                s0[ii][2] = fma2(cvS[3 + g], r2, s0[ii][2]);
                s0[ii][3] = fma2(cvS[3 + g], r3, s0[ii][3]);
            }
        }
        #pragma unroll
        for (int k = 0; k < 4; k++) {   // each k handles 2 tokens
            int t0 = c * 8 + k * 2;
            ull vA0, vB0, vA1, vB1;
            LDS2(vA0, vB0, vbAddr + t0 * 16);
            LDS2(vA1, vB1, vbAddr + t0 * 16 + 16);
            #pragma unroll
            for (int ii = 0; ii < 4; ii++) {
                float2 v = unpack2(s0[ii][k]);
                float e0 = ex2(v.x);
                float e1 = ex2(v.y);
                ssum[ii] += e0 + e1;
                ull e02 = pack2(e0, e0);
                ull e12 = pack2(e1, e1);
                aA[ii] = fma2(e02, vA0, aA[ii]); aB[ii] = fma2(e02, vB0, aB[ii]);
                aA[ii] = fma2(e12, vA1, aA[ii]); aB[ii] = fma2(e12, vB1, aB[ii]);
            }
        }
    }

    // ---- bias + ctx per (ii,h) -> bc[ii][h] ----
    float bc[4][HH];
    #pragma unroll
    for (int ii = 0; ii < 4; ii++) {
        ull bA = pack2(sCbF[ii][0], sCbF[ii][1]);
        ull bB = pack2(sCbF[ii][2], sCbF[ii][3]);
        const uint32_t wa = wrbAddr + ii * (9 * HH * 4);
        ull wA, wB;
        LDS2(wA, wB, wa + 0 * 16);  bA = fma2(cvS[0], wA, bA); bB = fma2(cvS[0], wB, bB);
        LDS2(wA, wB, wa + 1 * 16);  bA = fma2(cvS[1], wA, bA); bB = fma2(cvS[1], wB, bB);
        LDS2(wA, wB, wa + 2 * 16);  bA = fma2(cvS[2], wA, bA); bB = fma2(cvS[2], wB, bB);
        LDS2(wA, wB, wa + 3 * 16);  bA = fma2(cvI[ii][0], wA, bA); bB = fma2(cvI[ii][0], wB, bB);
        LDS2(wA, wB, wa + 4 * 16);  bA = fma2(cvI[ii][1], wA, bA); bB = fma2(cvI[ii][1], wB, bB);
        LDS2(wA, wB, wa + 5 * 16);  bA = fma2(cvI[ii][2], wA, bA); bB = fma2(cvI[ii][2], wB, bB);
        LDS2(wA, wB, wa + 6 * 16);  bA = fma2(cvS[3], wA, bA); bB = fma2(cvS[3], wB, bB);
        LDS2(wA, wB, wa + 7 * 16);  bA = fma2(cvS[4], wA, bA); bB = fma2(cvS[4], wB, bB);
        LDS2(wA, wB, wa + 8 * 16);  bA = fma2(cvS[5], wA, bA); bB = fma2(cvS[5], wB, bB);
        float2 b01 = unpack2(bA), b23 = unpack2(bB);
        float invL = __fdividef(1.f, ssum[ii]) * LOG2E;
        float2 a01 = unpack2(aA[ii]), a23 = unpack2(aB[ii]);
        bc[ii][0] = b01.x + a01.x * invL;
        bc[ii][1] = b01.y + a01.y * invL;
        bc[ii][2] = b23.x + a23.x * invL;
        bc[ii][3] = b23.y + a23.y * invL;
    }

    // ---- QK per head: kk[16] K in regs, 4 ii chains, fused exp, float4-over-ii store ----
    const float SC = 0.17677669529663687f * LOG2E;  // 1/sqrt(32) * log2(e)
    #pragma unroll
    for (int h = 0; h < HH; h++) {
        const float* kc = g_kT + (size_t)(b * HH + h) * DD * NN + j;
        ull kk[16];
        #pragma unroll
        for (int d2 = 0; d2 < 16; d2++)
            kk[d2] = pack2(kc[(2 * d2) * NN], kc[(2 * d2 + 1) * NN]);
        float ev[4];
        #pragma unroll
        for (int ii = 0; ii < 4; ii++) {
            ull acc = 0ull;
            #pragma unroll
            for (int d2 = 0; d2 < 16; d2 += 2) {
                ull q0, q1;
                LDS2(q0, q1, qpAddr + ((ii * HH + h) * 16 + d2) * 8);
                acc = fma2(kk[d2], q0, acc);
                acc = fma2(kk[d2 + 1], q1, acc);
            }
            float2 r = unpack2(acc);
            ev[ii] = ex2((r.x + r.y) * SC + bc[ii][h]);
        }
        sEn[tid][h] = make_float4(ev[0], ev[1], ev[2], ev[3]);
    }
    __syncthreads();

    // ---- AV: V loads shared by 4 i; one broadcast LDS.128 per (jj) ----
    const int wid = tid >> 5, lane = tid & 31;
    {
        const int h = lane >> 3, d4 = lane & 7;
        const float* vp = g_v + (size_t)(b * HH + h) * NN * DD + d4 * 4;
        ull acc[4][2] = {{0,0},{0,0},{0,0},{0,0}};
        float eacc[4] = {0.f, 0.f, 0.f, 0.f};
        #pragma unroll 8
        for (int jj = 0; jj < 32; jj++) {
            int j2 = wid * 32 + jj;
            ull vA, vB;
            LDG2(vA, vB, vp + (size_t)j2 * DD);
            float4 ev = sEn[j2][h];    // broadcast LDS.128: e for all 4 ii
            eacc[0] += ev.x; eacc[1] += ev.y; eacc[2] += ev.z; eacc[3] += ev.w;
            ull e2;
            e2 = pack2(ev.x, ev.x);
            acc[0][0] = fma2(e2, vA, acc[0][0]); acc[0][1] = fma2(e2, vB, acc[0][1]);
            e2 = pack2(ev.y, ev.y);
            acc[1][0] = fma2(e2, vA, acc[1][0]); acc[1][1] = fma2(e2, vB, acc[1][1]);
            e2 = pack2(ev.z, ev.z);
            acc[2][0] = fma2(e2, vA, acc[2][0]); acc[2][1] = fma2(e2, vB, acc[2][1]);
            e2 = pack2(ev.w, ev.w);
            acc[3][0] = fma2(e2, vA, acc[3][0]); acc[3][1] = fma2(e2, vB, acc[3][1]);
        }
        #pragma unroll
        for (int ii = 0; ii < 4; ii++) {
            ull* dst = (ull*)&sAVf[ii][wid][lane * 4];
            dst[0] = acc[ii][0]; dst[1] = acc[ii][1];
        }
        if (d4 == 0) {
            #pragma unroll
            for (int ii = 0; ii < 4; ii++) sESum[ii][wid][h] = eacc[ii];
        }
    }
    __syncthreads();
    // ---- normalize: 4 i x 128 c = 512 items, 2 per thread ----
    #pragma unroll
    for (int p = 0; p < 2; p++) {
        const int ii = (tid >> 7) * 2 + p;
        const int c = tid & 127;
        const int h = c >> 5, d = c & 31;
        float s = 0.f;
        float denom = 0.f;
        #pragma unroll
        for (int w = 0; w < 8; w++) {
            s += sAVf[ii][w][h * 32 + d];
            denom += sESum[ii][w][h];
        }
        sOFi[c * 4 + ii] = __fdividef(s, denom);
    }
    __syncthreads();

    // ---- output projection: one LDS2 serves all 4 i per Wo element ----
    {
        const int c = tid & 127;
        const int half = tid >> 7;
        const float* wp = Wo + (half * 64) * CC + c;
        const uint32_t ofAddr = (uint32_t)__cvta_generic_to_shared(sOFi4) + half * 64 * 16;
        ull accA = 0ull, accB = 0ull;
        #pragma unroll 8
        for (int cc2 = 0; cc2 < 64; cc2++) {
            float w = wp[cc2 * CC];
            ull o01, o23;
            LDS2(o01, o23, ofAddr + cc2 * 16);
            ull w2 = pack2(w, w);
            accA = fma2(o01, w2, accA);
            accB = fma2(o23, w2, accB);
        }
        float2 rA = unpack2(accA), rB = unpack2(accB);
        sOP[0][half][c] = rA.x;
        sOP[1][half][c] = rA.y;
        sOP[2][half][c] = rB.x;
        sOP[3][half][c] = rB.y;
    }
    __syncthreads();
    #pragma unroll
    for (int p = 0; p < 2; p++) {
        const int ii = (tid >> 7) * 2 + p;
        const int c = tid & 127;
        out[(b * NN + i0 + ii) * CC + c] = bo[c] + sOP[ii][0][c] + sOP[ii][1][c];
    }
}

// ---------------- launch ----------------
extern "C" void kernel_launch(void* const* d_in, const int* in_sizes, int n_in,
                              void* d_out, int out_size)
{
    const float* feat    = (const float*)d_in[0];
    const float* centers = (const float*)d_in[1];
    const float* corners = (const float*)d_in[2];
    const float* lang    = (const float*)d_in[3];
    const float* Wq    = (const float*)d_in[4];
    const float* bq    = (const float*)d_in[5];
    const float* Wk    = (const float*)d_in[6];
    const float* bk    = (const float*)d_in[7];
    const float* Wv    = (const float*)d_in[8];
    const float* bv    = (const float*)d_in[9];
    const float* Wo    = (const float*)d_in[10];
    const float* bo    = (const float*)d_in[11];
    const float* Wrel  = (const float*)d_in[12];
    const float* brel  = (const float*)d_in[13];
    const float* Wtk   = (const float*)d_in[14];
    const float* btk   = (const float*)d_in[15];
    const float* Wtv   = (const float*)d_in[16];
    const float* btv   = (const float*)d_in[17];
    const float* Wbias = (const float*)d_in[18];
    const float* bbias = (const float*)d_in[19];

    k_combos<<<281, 256>>>(Wtk, btk, Wtv, btv, Wrel, brel, Wbias, bbias);
    k_lang<<<BB * TT, 128>>>(lang);
    k_qkv<<<BB * NN / 8, 256>>>(feat, corners, Wq, bq, Wk, bk, Wv, bv);
    k_main<<<dim3(NN / 4, BB), 256>>>(centers, Wo, bo, (float*)d_out);
}